// round 4
// baseline (speedup 1.0000x reference)
#include <cuda_runtime.h>
#include <cstdint>

#define C_IN   256
#define C_OUT  256
#define HDIM   56
#define WDIM   56
#define BATCH  32
#define HW     (HDIM*WDIM)        // 3136
#define PG     64                 // padded grid stride (64x64 per image)
#define GUARD  64
#define NVEC   (GUARD + BATCH*PG*PG + GUARD)   // 131200 activation vectors

// ---------------- scratch (no allocations allowed) ----------------
__device__ __align__(128) int8_t g_P[(size_t)NVEC * C_IN];      // padded +-1 acts, 33.6 MB
__device__ __align__(128) int8_t g_WB[9 * C_OUT * C_IN];        // +-1 weights [tap][co][ci]
__device__ float g_sa[C_OUT];                                   // alpha*scale

// ---------------------------------------------------------------------------
// 1) Weight prep
// ---------------------------------------------------------------------------
__global__ void prep_weights(const float* __restrict__ W,
                             const float* __restrict__ RV,
                             const float* __restrict__ alpha) {
    const int co = blockIdx.x;
    const int ci = threadIdx.x;
    const float r0 = RV[0], r1 = RV[1], r2 = RV[2], r3 = RV[3];
    const int sk = C_OUT * C_IN * 9;
    const float* base = W + ((size_t)co * C_IN + ci) * 9;

    float asum = 0.f;
#pragma unroll
    for (int tap = 0; tap < 9; ++tap) {
        float v = r0 * base[tap] + r1 * base[sk + tap]
                + r2 * base[2 * sk + tap] + r3 * base[3 * sk + tap];
        asum += fabsf(v);
        g_WB[((size_t)tap * C_OUT + co) * C_IN + ci] = (v >= 0.f) ? 1 : -1;
    }
    __shared__ float red[256];
    red[ci] = asum;
    __syncthreads();
    for (int s = 128; s > 0; s >>= 1) {
        if (ci < s) red[ci] += red[ci + s];
        __syncthreads();
    }
    if (ci == 0) g_sa[co] = alpha[co] * (red[0] * (1.0f / 2304.0f));
}

// ---------------------------------------------------------------------------
// 2) Activation pack: P[vec][ci] = sign(x) as int8 +-1 inside image, 0 outside.
// ---------------------------------------------------------------------------
__global__ void pack_P(const float* __restrict__ x) {
    const int v = blockIdx.x * blockDim.x + threadIdx.x;
    if (v >= NVEC) return;
    const int vi = v - GUARD;
    bool img = false;
    int b = 0, h = 0, w = 0;
    if (vi >= 0 && vi < BATCH * PG * PG) {
        b = vi >> 12;
        const int r = (vi >> 6) & 63, c = vi & 63;
        if (r >= 1 && r <= 56 && c >= 1 && c <= 56) { img = true; h = r - 1; w = c - 1; }
    }
    uint4* dst = reinterpret_cast<uint4*>(g_P + (size_t)v * 256);
    if (!img) {
        const uint4 z = make_uint4(0, 0, 0, 0);
#pragma unroll
        for (int i = 0; i < 16; ++i) dst[i] = z;
    } else {
        const float* xp = x + (size_t)b * C_IN * HW + h * WDIM + w;
#pragma unroll
        for (int i = 0; i < 16; ++i) {
            uint32_t pk[4];
#pragma unroll
            for (int j = 0; j < 4; ++j) {
                uint32_t word = 0;
#pragma unroll
                for (int t = 0; t < 4; ++t) {
                    float vv = __ldg(xp + (size_t)(i * 16 + j * 4 + t) * HW);
                    word |= (uint32_t)((vv >= 0.f) ? 0x01u : 0xFFu) << (8 * t);
                }
                pk[j] = word;
            }
            dst[i] = make_uint4(pk[0], pk[1], pk[2], pk[3]);
        }
    }
}

// ---------------------------------------------------------------------------
// 3) Implicit-GEMM conv, 16 warps (4/SMSP) for latency hiding.
//    Tile: 128 px x 256 co; warp tile 32x64. A-union loaded once per CTA.
// ---------------------------------------------------------------------------
#define AU_ROWS 258
#define SM_A    (260 * 256)            // 66560 B
#define SM_B    65536                  // 256 co x 256 ci int8
#define SMEM_TOTAL (SM_A + 2 * SM_B)   // 197632 B
#define NTHR    512

static __device__ __forceinline__ uint32_t su32(const void* p) {
    return (uint32_t)__cvta_generic_to_shared(p);
}
static __device__ __forceinline__ uint32_t swz(uint32_t row, uint32_t g) {
    return (g & 8u) | ((g ^ row) & 7u);
}
static __device__ __forceinline__ void cpa16(uint32_t dst, const void* src) {
    asm volatile("cp.async.cg.shared.global [%0], [%1], 16;" :: "r"(dst), "l"(src));
}
static __device__ __forceinline__ void ldm4(uint32_t& r0, uint32_t& r1,
                                            uint32_t& r2, uint32_t& r3, uint32_t a) {
    asm volatile("ldmatrix.sync.aligned.m8n8.x4.shared.b16 {%0,%1,%2,%3}, [%4];"
                 : "=r"(r0), "=r"(r1), "=r"(r2), "=r"(r3) : "r"(a));
}
static __device__ __forceinline__ void mma8(int* d, const uint32_t* a,
                                            uint32_t b0, uint32_t b1) {
    asm volatile(
        "mma.sync.aligned.m16n8k32.row.col.s32.s8.s8.s32 "
        "{%0,%1,%2,%3}, {%4,%5,%6,%7}, {%8,%9}, {%0,%1,%2,%3};"
        : "+r"(d[0]), "+r"(d[1]), "+r"(d[2]), "+r"(d[3])
        : "r"(a[0]), "r"(a[1]), "r"(a[2]), "r"(a[3]), "r"(b0), "r"(b1));
}

__global__ void __launch_bounds__(NTHR, 1) conv_mma(float* __restrict__ out) {
    extern __shared__ __align__(1024) char smem[];
    const uint32_t Abase = su32(smem);
    const uint32_t Bbase = Abase + SM_A;

    const int tid  = threadIdx.x;
    const int lane = tid & 31;
    const int warp = tid >> 5;
    const int wm   = warp & 3;          // 4 warps along M (32 px each)
    const int wn   = warp >> 2;         // 4 warps along N (64 co each)

    const int tile = blockIdx.x;        // 896 = 32 images x 28 row-pairs
    const int b    = tile / 28;
    const int rp   = tile - b * 28;
    const int oh0  = 1 + 2 * rp;        // padded rows oh0, oh0+1
    const long q0  = GUARD + (long)b * (PG * PG) + (long)oh0 * PG;

    // ---- A-union: rows q0-65 .. q0+192 (258 vectors) ----
    {
        const int8_t* src0 = g_P + (q0 - 65) * 256;
        for (int i = tid; i < AU_ROWS * 16; i += NTHR) {
            const uint32_t row = i >> 4, g = i & 15;
            cpa16(Abase + row * 256 + swz(row, g) * 16, src0 + (size_t)row * 256 + g * 16);
        }
        asm volatile("cp.async.commit_group;" ::: "memory");
    }
    auto load_B = [&](int tap, int buf) {
        const int8_t* src0 = g_WB + (size_t)tap * (C_OUT * 256);
        const uint32_t dst0 = Bbase + buf * SM_B;
#pragma unroll
        for (int i = 0; i < 8; ++i) {
            const uint32_t u = tid + NTHR * i;
            const uint32_t co = u >> 4, g = u & 15;
            cpa16(dst0 + co * 256 + swz(co, g) * 16, src0 + (size_t)co * 256 + g * 16);
        }
        asm volatile("cp.async.commit_group;" ::: "memory");
    };
    load_B(0, 0);

    int c[2][8][4];
#pragma unroll
    for (int i = 0; i < 2; ++i)
#pragma unroll
        for (int j = 0; j < 8; ++j)
#pragma unroll
            for (int k = 0; k < 4; ++k) c[i][j][k] = 0;

    const uint32_t aRow0 = 32u * wm + (lane & 15);     // + shift + 16*mi
    const uint32_t aKhi  = (uint32_t)(lane >> 4);
    const uint32_t bCo0  = 64u * wn + (lane & 7) + ((lane >> 4) & 1) * 8;
    const uint32_t bKhi  = (uint32_t)((lane >> 3) & 1);

    for (int tap = 0; tap < 9; ++tap) {
        if (tap < 8) load_B(tap + 1, (tap + 1) & 1);
        if (tap < 8) asm volatile("cp.async.wait_group 1;" ::: "memory");
        else         asm volatile("cp.async.wait_group 0;" ::: "memory");
        __syncthreads();

        const uint32_t shift = (uint32_t)((tap / 3) * 64 + (tap % 3));
        const uint32_t Bcur  = Bbase + (tap & 1) * SM_B;

#pragma unroll
        for (int ks = 0; ks < 8; ++ks) {
            uint32_t a[2][4];
#pragma unroll
            for (int mi = 0; mi < 2; ++mi) {
                const uint32_t row = shift + aRow0 + 16u * mi;
                const uint32_t kg  = 2u * ks + aKhi;
                ldm4(a[mi][0], a[mi][1], a[mi][2], a[mi][3],
                     Abase + row * 256 + swz(row, kg) * 16);
            }
#pragma unroll
            for (int njp = 0; njp < 4; ++njp) {
                uint32_t bb[4];
                const uint32_t co = bCo0 + 16u * njp;
                const uint32_t kg = 2u * ks + bKhi;
                ldm4(bb[0], bb[1], bb[2], bb[3],
                     Bcur + co * 256 + swz(co, kg) * 16);
#pragma unroll
                for (int mi = 0; mi < 2; ++mi) {
                    mma8(c[mi][2 * njp],     a[mi], bb[0], bb[1]);
                    mma8(c[mi][2 * njp + 1], a[mi], bb[2], bb[3]);
                }
            }
        }
        __syncthreads();   // protect buf (tap&1) before reload at tap+2
    }

    // ---- epilogue: scale + direct stores ----
    float sa2[8][2];
#pragma unroll
    for (int nj = 0; nj < 8; ++nj) {
        const int co = 64 * wn + 8 * nj + (lane & 3) * 2;
        sa2[nj][0] = __ldg(&g_sa[co]);
        sa2[nj][1] = __ldg(&g_sa[co + 1]);
    }
    float* ob = out + (size_t)b * C_OUT * HW;

#pragma unroll
    for (int mi = 0; mi < 2; ++mi) {
#pragma unroll
        for (int rh = 0; rh < 2; ++rh) {
            const int m  = 32 * wm + 16 * mi + (lane >> 2) + 8 * rh;
            const int ow = m & 63;
            if (ow < 1 || ow > 56) continue;
            const int oh = oh0 + (m >> 6);
            const long poff = (long)(oh - 1) * WDIM + (ow - 1);
#pragma unroll
            for (int nj = 0; nj < 8; ++nj) {
                const int co = 64 * wn + 8 * nj + (lane & 3) * 2;
                const long o0 = (long)co * HW + poff;
                ob[o0]      = __int2float_rn(c[mi][nj][2 * rh])     * sa2[nj][0];
                ob[o0 + HW] = __int2float_rn(c[mi][nj][2 * rh + 1]) * sa2[nj][1];
            }
        }
    }
}

// ---------------------------------------------------------------------------
extern "C" void kernel_launch(void* const* d_in, const int* in_sizes, int n_in,
                              void* d_out, int out_size) {
    const float* x     = (const float*)d_in[0];
    const float* W     = (const float*)d_in[1];
    const float* RV    = (const float*)d_in[2];
    const float* alpha = (const float*)d_in[3];
    float* out         = (float*)d_out;

    cudaFuncSetAttribute(conv_mma,
                         cudaFuncAttributeMaxDynamicSharedMemorySize, SMEM_TOTAL);

    prep_weights<<<C_OUT, 256>>>(W, RV, alpha);
    pack_P<<<(NVEC + 255) / 256, 256>>>(x);
    conv_mma<<<BATCH * 28, NTHR, SMEM_TOTAL>>>(out);
}

// round 6
// speedup vs baseline: 1.0168x; 1.0168x over previous
#include <cuda_runtime.h>
#include <cstdint>

#define C_IN   256
#define C_OUT  256
#define HDIM   56
#define WDIM   56
#define BATCH  32
#define HW     (HDIM*WDIM)        // 3136
#define PG     64                 // padded grid stride (64x64 per image)
#define GUARD  64
#define NVEC   (GUARD + BATCH*PG*PG + GUARD)   // 131200 activation vectors

// ---------------- scratch (no allocations allowed) ----------------
__device__ __align__(128) int8_t g_P[(size_t)NVEC * C_IN];      // padded +-1 acts, 33.6 MB
__device__ __align__(128) int8_t g_WB[9 * C_OUT * C_IN];        // +-1 weights [tap][co][ci]
__device__ float g_sa[C_OUT];                                   // alpha*scale

// ---------------------------------------------------------------------------
// 1) Weight prep
// ---------------------------------------------------------------------------
__global__ void prep_weights(const float* __restrict__ W,
                             const float* __restrict__ RV,
                             const float* __restrict__ alpha) {
    const int co = blockIdx.x;
    const int ci = threadIdx.x;
    const float r0 = RV[0], r1 = RV[1], r2 = RV[2], r3 = RV[3];
    const int sk = C_OUT * C_IN * 9;
    const float* base = W + ((size_t)co * C_IN + ci) * 9;

    float asum = 0.f;
#pragma unroll
    for (int tap = 0; tap < 9; ++tap) {
        float v = r0 * base[tap] + r1 * base[sk + tap]
                + r2 * base[2 * sk + tap] + r3 * base[3 * sk + tap];
        asum += fabsf(v);
        g_WB[((size_t)tap * C_OUT + co) * C_IN + ci] = (v >= 0.f) ? 1 : -1;
    }
    __shared__ float red[256];
    red[ci] = asum;
    __syncthreads();
    for (int s = 128; s > 0; s >>= 1) {
        if (ci < s) red[ci] += red[ci + s];
        __syncthreads();
    }
    if (ci == 0) g_sa[co] = alpha[co] * (red[0] * (1.0f / 2304.0f));
}

// ---------------------------------------------------------------------------
// 2) Activation pack: P[vec][ci] = sign(x) as int8 +-1 inside image, 0 outside.
// ---------------------------------------------------------------------------
__global__ void pack_P(const float* __restrict__ x) {
    const int v = blockIdx.x * blockDim.x + threadIdx.x;
    if (v >= NVEC) return;
    const int vi = v - GUARD;
    bool img = false;
    int b = 0, h = 0, w = 0;
    if (vi >= 0 && vi < BATCH * PG * PG) {
        b = vi >> 12;
        const int r = (vi >> 6) & 63, c = vi & 63;
        if (r >= 1 && r <= 56 && c >= 1 && c <= 56) { img = true; h = r - 1; w = c - 1; }
    }
    uint4* dst = reinterpret_cast<uint4*>(g_P + (size_t)v * 256);
    if (!img) {
        const uint4 z = make_uint4(0, 0, 0, 0);
#pragma unroll
        for (int i = 0; i < 16; ++i) dst[i] = z;
    } else {
        const float* xp = x + (size_t)b * C_IN * HW + h * WDIM + w;
#pragma unroll
        for (int i = 0; i < 16; ++i) {
            uint32_t pk[4];
#pragma unroll
            for (int j = 0; j < 4; ++j) {
                uint32_t word = 0;
#pragma unroll
                for (int t = 0; t < 4; ++t) {
                    float vv = __ldg(xp + (size_t)(i * 16 + j * 4 + t) * HW);
                    word |= (uint32_t)((vv >= 0.f) ? 0x01u : 0xFFu) << (8 * t);
                }
                pk[j] = word;
            }
            dst[i] = make_uint4(pk[0], pk[1], pk[2], pk[3]);
        }
    }
}

// ---------------------------------------------------------------------------
// 3) Implicit-GEMM conv, M = 112 VALID pixels (2 image rows), zero M-waste.
//    14 warps: 7 M-strips (16 px) x 2 N-halves (128 co). Per-lane ldmatrix
//    addressing maps tile rows onto the padded union, skipping pad columns.
// ---------------------------------------------------------------------------
#define AU_ROWS 256
#define SM_A    (AU_ROWS * 256)        // 65536 B
#define SM_B    65536                  // 256 co x 256 ci int8
#define SMEM_TOTAL (SM_A + 2 * SM_B)   // 196608 B
#define NTHR    448

static __device__ __forceinline__ uint32_t su32(const void* p) {
    return (uint32_t)__cvta_generic_to_shared(p);
}
static __device__ __forceinline__ uint32_t swz(uint32_t row, uint32_t g) {
    return (g & 8u) | ((g ^ row) & 7u);
}
static __device__ __forceinline__ void cpa16(uint32_t dst, const void* src) {
    asm volatile("cp.async.cg.shared.global [%0], [%1], 16;" :: "r"(dst), "l"(src));
}
static __device__ __forceinline__ void ldm4(uint32_t& r0, uint32_t& r1,
                                            uint32_t& r2, uint32_t& r3, uint32_t a) {
    asm volatile("ldmatrix.sync.aligned.m8n8.x4.shared.b16 {%0,%1,%2,%3}, [%4];"
                 : "=r"(r0), "=r"(r1), "=r"(r2), "=r"(r3) : "r"(a));
}
static __device__ __forceinline__ void mma8(int* d, const uint32_t* a,
                                            uint32_t b0, uint32_t b1) {
    asm volatile(
        "mma.sync.aligned.m16n8k32.row.col.s32.s8.s8.s32 "
        "{%0,%1,%2,%3}, {%4,%5,%6,%7}, {%8,%9}, {%0,%1,%2,%3};"
        : "+r"(d[0]), "+r"(d[1]), "+r"(d[2]), "+r"(d[3])
        : "r"(a[0]), "r"(a[1]), "r"(a[2]), "r"(a[3]), "r"(b0), "r"(b1));
}

__global__ void __launch_bounds__(NTHR, 1) conv_mma(float* __restrict__ out) {
    extern __shared__ __align__(1024) char smem[];
    const uint32_t Abase = su32(smem);
    const uint32_t Bbase = Abase + SM_A;

    const int tid  = threadIdx.x;
    const int lane = tid & 31;
    const int warp = tid >> 5;
    const int wm   = warp % 7;          // M strip: 16 valid pixels
    const int wn   = warp / 7;          // N half: 128 co

    const int tile = blockIdx.x;        // 896 = 32 images x 28 row-pairs
    const int b    = tile / 28;
    const int rp   = tile - b * 28;
    // q0 = padded vector of (image row 2*rp, padded col 0)
    const long q0  = GUARD + (long)b * (PG * PG) + (long)(2 * rp + 1) * PG;

    // per-lane A row within the union: tile row m -> (m/56)*64 + m%56 + 1,
    // union loaded from q0-65 so smem row = that + shift(tap), shift>=0.
    const int m_lane = 16 * wm + (lane & 15);
    const uint32_t prow = (uint32_t)((m_lane / 56) * 64 + (m_lane % 56) + 1);
    const uint32_t aKhi = (uint32_t)(lane >> 4);
    const uint32_t bCo0 = 128u * wn + (lane & 7) + ((lane >> 4) & 1) * 8;
    const uint32_t bKhi = (uint32_t)((lane >> 3) & 1);

    // ---- A-union: 256 vectors starting at q0-65 ----
    {
        const int8_t* src0 = g_P + (q0 - 65) * 256;
        for (int i = tid; i < AU_ROWS * 16; i += NTHR) {
            const uint32_t row = i >> 4, g = i & 15;
            cpa16(Abase + row * 256 + swz(row, g) * 16, src0 + (size_t)row * 256 + g * 16);
        }
        asm volatile("cp.async.commit_group;" ::: "memory");
    }
    auto load_B = [&](int tap, int buf) {
        const int8_t* src0 = g_WB + (size_t)tap * (C_OUT * 256);
        const uint32_t dst0 = Bbase + buf * SM_B;
        for (int i = tid; i < 4096; i += NTHR) {
            const uint32_t co = i >> 4, g = i & 15;
            cpa16(dst0 + co * 256 + swz(co, g) * 16, src0 + (size_t)co * 256 + g * 16);
        }
        asm volatile("cp.async.commit_group;" ::: "memory");
    };
    load_B(0, 0);

    int c[16][4];
#pragma unroll
    for (int j = 0; j < 16; ++j)
#pragma unroll
        for (int k = 0; k < 4; ++k) c[j][k] = 0;

    for (int tap = 0; tap < 9; ++tap) {
        if (tap < 8) load_B(tap + 1, (tap + 1) & 1);
        if (tap < 8) asm volatile("cp.async.wait_group 1;" ::: "memory");
        else         asm volatile("cp.async.wait_group 0;" ::: "memory");
        __syncthreads();

        const uint32_t shift = (uint32_t)((tap / 3) * 64 + (tap % 3));
        const uint32_t Bcur  = Bbase + (tap & 1) * SM_B;
        const uint32_t aRow  = prow + shift;

#pragma unroll
        for (int ks = 0; ks < 8; ++ks) {
            uint32_t a[4];
            {
                const uint32_t kg = 2u * ks + aKhi;
                ldm4(a[0], a[1], a[2], a[3],
                     Abase + aRow * 256 + swz(aRow, kg) * 16);
            }
#pragma unroll
            for (int njp = 0; njp < 8; ++njp) {
                uint32_t bb[4];
                const uint32_t co = bCo0 + 16u * njp;
                const uint32_t kg = 2u * ks + bKhi;
                ldm4(bb[0], bb[1], bb[2], bb[3],
                     Bcur + co * 256 + swz(co, kg) * 16);
                mma8(c[2 * njp],     a, bb[0], bb[1]);
                mma8(c[2 * njp + 1], a, bb[2], bb[3]);
            }
        }
        __syncthreads();   // protect buf (tap&1) before reload at tap+2
    }

    // ---- epilogue: scale + direct stores, every row valid ----
    float* ob = out + (size_t)b * C_OUT * HW;
#pragma unroll
    for (int rh = 0; rh < 2; ++rh) {
        const int m  = 16 * wm + (lane >> 2) + 8 * rh;
        const int oh = 2 * rp + m / 56;
        const int ow = m % 56;
        const long poff = (long)oh * WDIM + ow;
#pragma unroll
        for (int nj = 0; nj < 16; ++nj) {
            const int co = 128 * wn + 8 * nj + (lane & 3) * 2;
            const float s0 = __ldg(&g_sa[co]);
            const float s1 = __ldg(&g_sa[co + 1]);
            const long o0 = (long)co * HW + poff;
            ob[o0]      = __int2float_rn(c[nj][2 * rh])     * s0;
            ob[o0 + HW] = __int2float_rn(c[nj][2 * rh + 1]) * s1;
        }
    }
}

// ---------------------------------------------------------------------------
extern "C" void kernel_launch(void* const* d_in, const int* in_sizes, int n_in,
                              void* d_out, int out_size) {
    const float* x     = (const float*)d_in[0];
    const float* W     = (const float*)d_in[1];
    const float* RV    = (const float*)d_in[2];
    const float* alpha = (const float*)d_in[3];
    float* out         = (float*)d_out;

    cudaFuncSetAttribute(conv_mma,
                         cudaFuncAttributeMaxDynamicSharedMemorySize, SMEM_TOTAL);

    prep_weights<<<C_OUT, 256>>>(W, RV, alpha);
    pack_P<<<(NVEC + 255) / 256, 256>>>(x);
    conv_mma<<<BATCH * 28, NTHR, SMEM_TOTAL>>>(out);
}